// round 4
// baseline (speedup 1.0000x reference)
#include <cuda_runtime.h>

// DiffJPEG forward: out = jpeg_compress(clip(x,0,1), quality=75)
// x, out: (16, 3, 512, 512) float32
//
// One CTA per 64x64 pixel tile, 96 threads:
//   threads [0,64): one full 8x8 luma block per thread (register-resident)
//   threads [64,96): one full 8x8 chroma block per thread (2 ch x 4x4 blocks)
// DCT/quant/IDCT entirely in registers via even/odd butterflies; quant table
// folded to immediates. SMEM only for the luma->chroma handoff.

#define IMG_H 512
#define IMG_W 512
#define BATCH 16

#define A1 0.4903926402016152f
#define A2 0.4619397662556434f
#define A3 0.4157348061512726f
#define A4 0.3535533905932738f
#define A5 0.2777851165098011f
#define A6 0.1913417161825449f
#define A7 0.0975451610080642f

__device__ constexpr float QYt[8][8] = {
    {16, 11, 10, 16, 24, 40, 51, 61},
    {12, 12, 14, 19, 26, 58, 60, 55},
    {14, 13, 16, 24, 40, 57, 69, 56},
    {14, 17, 22, 29, 51, 87, 80, 62},
    {18, 22, 37, 56, 68, 109, 103, 77},
    {24, 35, 55, 64, 81, 104, 113, 92},
    {49, 64, 78, 87, 103, 121, 120, 101},
    {72, 92, 95, 98, 112, 100, 103, 99},
};
__device__ constexpr float QCt[8][8] = {
    {17, 18, 24, 47, 99, 99, 99, 99},
    {18, 21, 26, 66, 99, 99, 99, 99},
    {24, 26, 56, 99, 99, 99, 99, 99},
    {47, 66, 99, 99, 99, 99, 99, 99},
    {99, 99, 99, 99, 99, 99, 99, 99},
    {99, 99, 99, 99, 99, 99, 99, 99},
    {99, 99, 99, 99, 99, 99, 99, 99},
    {99, 99, 99, 99, 99, 99, 99, 99},
};

// forward 8-point DCT-II (rows of D), in place
__device__ __forceinline__ void fwd1d(float d[8])
{
    float s0 = d[0] + d[7], s1 = d[1] + d[6], s2 = d[2] + d[5], s3 = d[3] + d[4];
    float t0 = d[0] - d[7], t1 = d[1] - d[6], t2 = d[2] - d[5], t3 = d[3] - d[4];
    d[0] = A4 * (s0 + s1 + s2 + s3);
    d[2] = A2 * s0 + A6 * s1 - A6 * s2 - A2 * s3;
    d[4] = A4 * (s0 - s1 - s2 + s3);
    d[6] = A6 * s0 - A2 * s1 + A2 * s2 - A6 * s3;
    d[1] = A1 * t0 + A3 * t1 + A5 * t2 + A7 * t3;
    d[3] = A3 * t0 - A7 * t1 - A1 * t2 - A5 * t3;
    d[5] = A5 * t0 - A1 * t1 + A7 * t2 + A3 * t3;
    d[7] = A7 * t0 - A5 * t1 + A3 * t2 - A1 * t3;
}

// inverse: r[x] = sum_u D[u][x] c[u], in place
__device__ __forceinline__ void inv1d(float d[8])
{
    float e0 = A4 * d[0] + A2 * d[2] + A4 * d[4] + A6 * d[6];
    float e1 = A4 * d[0] + A6 * d[2] - A4 * d[4] - A2 * d[6];
    float e2 = A4 * d[0] - A6 * d[2] - A4 * d[4] + A2 * d[6];
    float e3 = A4 * d[0] - A2 * d[2] + A4 * d[4] - A6 * d[6];
    float o0 = A1 * d[1] + A3 * d[3] + A5 * d[5] + A7 * d[7];
    float o1 = A3 * d[1] - A7 * d[3] - A1 * d[5] - A5 * d[7];
    float o2 = A5 * d[1] - A1 * d[3] + A7 * d[5] + A3 * d[7];
    float o3 = A7 * d[1] - A5 * d[3] + A3 * d[5] - A1 * d[7];
    d[0] = e0 + o0; d[7] = e0 - o0;
    d[1] = e1 + o1; d[6] = e1 - o1;
    d[2] = e2 + o2; d[5] = e2 - o2;
    d[3] = e3 + o3; d[4] = e3 - o3;
}

// full 8x8: fwd rows; per column fwd + quantize + inv; inv rows. In registers.
__device__ __forceinline__ void transform_block(float v[8][8], const bool isY)
{
#pragma unroll
    for (int i = 0; i < 8; i++) fwd1d(v[i]);
#pragma unroll
    for (int j = 0; j < 8; j++) {
        float c[8];
#pragma unroll
        for (int i = 0; i < 8; i++) c[i] = v[i][j];
        fwd1d(c);
#pragma unroll
        for (int u = 0; u < 8; u++) {
            const float qy  = QYt[u][j] * 0.5f;          // quality 75 -> factor 0.5
            const float qc  = QCt[u][j] * 0.5f;
            const float qyi = 1.0f / (QYt[u][j] * 0.5f);
            const float qci = 1.0f / (QCt[u][j] * 0.5f);
            float q  = isY ? qy  : qc;
            float qi = isY ? qyi : qci;
            c[u] = rintf(c[u] * qi) * q;
        }
        inv1d(c);
#pragma unroll
        for (int i = 0; i < 8; i++) v[i][j] = c[i];
    }
#pragma unroll
    for (int i = 0; i < 8; i++) inv1d(v[i]);
}

__global__ __launch_bounds__(96)
void diffjpeg_kernel(const float* __restrict__ x, float* __restrict__ out)
{
    // chroma handoff: holds full-res-averaged (downsampled) chroma partials,
    // then overwritten in place by reconstructed (centered) chroma.
    __shared__ __align__(16) float sC[2][32][36];

    const int tid = threadIdx.x;
    const int bx0 = blockIdx.x * 64;
    const int by0 = blockIdx.y * 64;
    const size_t plane = (size_t)IMG_H * IMG_W;
    const size_t ibase = (size_t)blockIdx.z * 3 * plane;

    const bool isY = (tid < 64);

    float v[8][8];

    // thread-geometry
    const int brow = tid >> 3, bcol = tid & 7;            // luma block coords
    const int ct   = tid - 64;
    const int ch   = ct >> 4;                              // chroma channel
    const int cidx = ct & 15;
    const int cbr  = cidx >> 2, cbc = cidx & 3;            // chroma block coords

    if (isY) {
        const float* p = x + ibase + (size_t)(by0 + brow * 8) * IMG_W + (bx0 + bcol * 8);
        float cbp[4], crp[4];
#pragma unroll
        for (int j = 0; j < 8; j++) {
            const float* pr = p + (size_t)j * IMG_W;
            float4 R0 = *(const float4*)pr;
            float4 R1 = *(const float4*)(pr + 4);
            float4 G0 = *(const float4*)(pr + plane);
            float4 G1 = *(const float4*)(pr + plane + 4);
            float4 B0 = *(const float4*)(pr + 2 * plane);
            float4 B1 = *(const float4*)(pr + 2 * plane + 4);
            float R[8] = {R0.x, R0.y, R0.z, R0.w, R1.x, R1.y, R1.z, R1.w};
            float G[8] = {G0.x, G0.y, G0.z, G0.w, G1.x, G1.y, G1.z, G1.w};
            float B[8] = {B0.x, B0.y, B0.z, B0.w, B1.x, B1.y, B1.z, B1.w};
            float cb[8], cr[8];
#pragma unroll
            for (int k = 0; k < 8; k++) {
                float rr = fminf(fmaxf(R[k], 0.f), 1.f) * 255.f;
                float gg = fminf(fmaxf(G[k], 0.f), 1.f) * 255.f;
                float bb = fminf(fmaxf(B[k], 0.f), 1.f) * 255.f;
                v[j][k] =  0.299f    * rr + 0.587f    * gg + 0.114f    * bb - 128.f;
                cb[k]   = -0.168736f * rr - 0.331264f * gg + 0.5f      * bb + 128.f;
                cr[k]   =  0.5f      * rr - 0.418688f * gg - 0.081312f * bb + 128.f;
            }
            float cbh[4] = {cb[0] + cb[1], cb[2] + cb[3], cb[4] + cb[5], cb[6] + cb[7]};
            float crh[4] = {cr[0] + cr[1], cr[2] + cr[3], cr[4] + cr[5], cr[6] + cr[7]};
            if ((j & 1) == 0) {
#pragma unroll
                for (int c = 0; c < 4; c++) { cbp[c] = cbh[c]; crp[c] = crh[c]; }
            } else {
                const int crow = brow * 4 + (j >> 1);
                float4 cq = make_float4(0.25f * (cbp[0] + cbh[0]) - 128.f,
                                        0.25f * (cbp[1] + cbh[1]) - 128.f,
                                        0.25f * (cbp[2] + cbh[2]) - 128.f,
                                        0.25f * (cbp[3] + cbh[3]) - 128.f);
                float4 rq = make_float4(0.25f * (crp[0] + crh[0]) - 128.f,
                                        0.25f * (crp[1] + crh[1]) - 128.f,
                                        0.25f * (crp[2] + crh[2]) - 128.f,
                                        0.25f * (crp[3] + crh[3]) - 128.f);
                *(float4*)&sC[0][crow][bcol * 4] = cq;
                *(float4*)&sC[1][crow][bcol * 4] = rq;
            }
        }
    }
    __syncthreads();

    if (isY) {
        transform_block(v, true);
    } else {
        // read own chroma block (centered), transform, write back in place
#pragma unroll
        for (int i = 0; i < 8; i++) {
            float4 a = *(const float4*)&sC[ch][cbr * 8 + i][cbc * 8];
            float4 b = *(const float4*)&sC[ch][cbr * 8 + i][cbc * 8 + 4];
            v[i][0] = a.x; v[i][1] = a.y; v[i][2] = a.z; v[i][3] = a.w;
            v[i][4] = b.x; v[i][5] = b.y; v[i][6] = b.z; v[i][7] = b.w;
        }
        transform_block(v, false);
#pragma unroll
        for (int i = 0; i < 8; i++) {
            *(float4*)&sC[ch][cbr * 8 + i][cbc * 8] =
                make_float4(v[i][0], v[i][1], v[i][2], v[i][3]);
            *(float4*)&sC[ch][cbr * 8 + i][cbc * 8 + 4] =
                make_float4(v[i][4], v[i][5], v[i][6], v[i][7]);
        }
    }
    __syncthreads();

    if (isY) {
        float* po = out + ibase + (size_t)(by0 + brow * 8) * IMG_W + (bx0 + bcol * 8);
#pragma unroll
        for (int j = 0; j < 8; j++) {
            const int crow = brow * 4 + (j >> 1);
            float4 cb4 = *(const float4*)&sC[0][crow][bcol * 4];
            float4 cr4 = *(const float4*)&sC[1][crow][bcol * 4];
            float cbm[8] = {cb4.x, cb4.x, cb4.y, cb4.y, cb4.z, cb4.z, cb4.w, cb4.w};
            float crm[8] = {cr4.x, cr4.x, cr4.y, cr4.y, cr4.z, cr4.z, cr4.w, cr4.w};
            float Rr[8], Gg[8], Bb[8];
#pragma unroll
            for (int k = 0; k < 8; k++) {
                float yv = v[j][k] + 128.f;
                float r2 = yv + 1.402f * crm[k];
                float g2 = yv - 0.344136f * cbm[k] - 0.714136f * crm[k];
                float b2 = yv + 1.772f * cbm[k];
                Rr[k] = fminf(fmaxf(r2, 0.f), 255.f) * (1.f / 255.f);
                Gg[k] = fminf(fmaxf(g2, 0.f), 255.f) * (1.f / 255.f);
                Bb[k] = fminf(fmaxf(b2, 0.f), 255.f) * (1.f / 255.f);
            }
            float* pw = po + (size_t)j * IMG_W;
            __stcs((float4*)pw,                 make_float4(Rr[0], Rr[1], Rr[2], Rr[3]));
            __stcs((float4*)(pw + 4),           make_float4(Rr[4], Rr[5], Rr[6], Rr[7]));
            __stcs((float4*)(pw + plane),       make_float4(Gg[0], Gg[1], Gg[2], Gg[3]));
            __stcs((float4*)(pw + plane + 4),   make_float4(Gg[4], Gg[5], Gg[6], Gg[7]));
            __stcs((float4*)(pw + 2 * plane),   make_float4(Bb[0], Bb[1], Bb[2], Bb[3]));
            __stcs((float4*)(pw + 2 * plane + 4), make_float4(Bb[4], Bb[5], Bb[6], Bb[7]));
        }
    }
}

extern "C" void kernel_launch(void* const* d_in, const int* in_sizes, int n_in,
                              void* d_out, int out_size)
{
    const float* x = (const float*)d_in[0];
    float* out = (float*)d_out;
    dim3 grid(IMG_W / 64, IMG_H / 64, BATCH);
    diffjpeg_kernel<<<grid, 96>>>(x, out);
}